// round 2
// baseline (speedup 1.0000x reference)
#include <cuda_runtime.h>

#define NHEAD 16
#define DK 64
#define SEQ 2048
#define BATCH 2
#define DMODEL 1024
#define BS (BATCH*SEQ)
#define NEGV -1000000000.0f

static const size_t OUT_ELEMS = (size_t)BATCH * SEQ * DMODEL;   // 4,194,304

// -------- scratch (static device globals; no runtime allocation) --------
__device__ float g_q[(size_t)BATCH * NHEAD * SEQ * DK];
__device__ float g_k[(size_t)BATCH * NHEAD * SEQ * DK];
__device__ float g_v[(size_t)BATCH * NHEAD * SEQ * DK];
__device__ float g_o[(size_t)BS * DMODEL];

// ---------------- helpers ----------------
__device__ __forceinline__ float warp_max(float v) {
    #pragma unroll
    for (int o = 16; o > 0; o >>= 1) v = fmaxf(v, __shfl_xor_sync(0xffffffffu, v, o));
    return v;
}
__device__ __forceinline__ float warp_sum(float v) {
    #pragma unroll
    for (int o = 16; o > 0; o >>= 1) v += __shfl_xor_sync(0xffffffffu, v, o);
    return v;
}

// ============================================================================
// Kernel 1: QKV projection.  C[4096,1024] = qkv @ W, written head-major
// [b][h][s][dk].  Q additionally scaled by 1/sqrt(dk)=0.125.
// Tiles: BM=128, BN=64 (one head), BK=16.  256 thr, 8x4 per thread.
// ============================================================================
__global__ __launch_bounds__(256)
void proj_kernel(const float* __restrict__ qkv,
                 const float* __restrict__ w_qs,
                 const float* __restrict__ w_ks,
                 const float* __restrict__ w_vs)
{
    const int mat = blockIdx.z;
    const float* W  = (mat == 0) ? w_qs : (mat == 1) ? w_ks : w_vs;
    float* out      = (mat == 0) ? g_q  : (mat == 1) ? g_k  : g_v;
    const float scale = (mat == 0) ? 0.125f : 1.0f;

    const int h  = blockIdx.x;          // head -> 64 output cols
    const int m0 = blockIdx.y * 128;    // row tile

    __shared__ float As[16][132];       // transposed A tile (pad 4)
    __shared__ float Bsm[16][64];       // W tile, natural

    const int tid = threadIdx.x;
    const int tx  = tid & 15;           // *4 cols
    const int ty  = tid >> 4;           // *8 rows

    float acc[8][4];
    #pragma unroll
    for (int i = 0; i < 8; i++)
        #pragma unroll
        for (int j = 0; j < 4; j++) acc[i][j] = 0.0f;

    for (int k0 = 0; k0 < DMODEL; k0 += 16) {
        // A tile: 128 rows x 16 cols -> As[k][m]
        #pragma unroll
        for (int t = 0; t < 2; t++) {
            int i4  = tid + t * 256;          // 0..511
            int row = i4 >> 2;                // 0..127
            int c4  = (i4 & 3) * 4;           // 0,4,8,12
            float4 v = *(const float4*)(qkv + (size_t)(m0 + row) * DMODEL + k0 + c4);
            As[c4 + 0][row] = v.x; As[c4 + 1][row] = v.y;
            As[c4 + 2][row] = v.z; As[c4 + 3][row] = v.w;
        }
        // W tile: 16 rows x 64 cols
        {
            int r  = tid >> 4;                // 0..15
            int c4 = (tid & 15) * 4;          // 0..60
            *(float4*)&Bsm[r][c4] =
                *(const float4*)(W + (size_t)(k0 + r) * DMODEL + h * 64 + c4);
        }
        __syncthreads();
        #pragma unroll
        for (int kk = 0; kk < 16; kk++) {
            float a[8], bb[4];
            *(float4*)(a)     = *(float4*)&As[kk][ty * 8];
            *(float4*)(a + 4) = *(float4*)&As[kk][ty * 8 + 4];
            *(float4*)(bb)    = *(float4*)&Bsm[kk][tx * 4];
            #pragma unroll
            for (int i = 0; i < 8; i++)
                #pragma unroll
                for (int j = 0; j < 4; j++) acc[i][j] = fmaf(a[i], bb[j], acc[i][j]);
        }
        __syncthreads();
    }
    #pragma unroll
    for (int i = 0; i < 8; i++) {
        int row = m0 + ty * 8 + i;
        int b = row >> 11;                    // /2048
        int s = row & 2047;
        float4 v = make_float4(acc[i][0] * scale, acc[i][1] * scale,
                               acc[i][2] * scale, acc[i][3] * scale);
        *(float4*)(out + ((size_t)((b * NHEAD + h) * SEQ + s)) * DK + tx * 4) = v;
    }
}

// ============================================================================
// Kernel 2: scores.  attn_raw[b,h,q,k] = (Q/temp) . K  masked with NEGV.
// Per (b,h): 2048x2048 GEMM over K=64.  Tiles BM=BN=128, BK=32, 8x8/thread.
// ============================================================================
__global__ __launch_bounds__(256)
void scores_kernel(const int* __restrict__ mask, float* __restrict__ attn)
{
    const int bh = blockIdx.z;
    const int b  = bh >> 4;
    const int q0 = blockIdx.y * 128;
    const int k0 = blockIdx.x * 128;

    __shared__ float Qs[32][132];
    __shared__ float Ks[32][132];

    const int tid = threadIdx.x;
    const int tx  = tid & 15;   // *8 cols
    const int ty  = tid >> 4;   // *8 rows

    float acc[8][8];
    #pragma unroll
    for (int i = 0; i < 8; i++)
        #pragma unroll
        for (int j = 0; j < 8; j++) acc[i][j] = 0.0f;

    const float* Qbase = g_q + (size_t)bh * SEQ * DK;
    const float* Kbase = g_k + (size_t)bh * SEQ * DK;

    for (int d0 = 0; d0 < DK; d0 += 32) {
        #pragma unroll
        for (int t = 0; t < 4; t++) {
            int i4  = tid + t * 256;
            int row = i4 >> 3;                // 8 float4 per row
            int c4  = (i4 & 7) * 4;
            float4 v = *(const float4*)(Qbase + (size_t)(q0 + row) * DK + d0 + c4);
            Qs[c4 + 0][row] = v.x; Qs[c4 + 1][row] = v.y;
            Qs[c4 + 2][row] = v.z; Qs[c4 + 3][row] = v.w;
        }
        #pragma unroll
        for (int t = 0; t < 4; t++) {
            int i4  = tid + t * 256;
            int row = i4 >> 3;
            int c4  = (i4 & 7) * 4;
            float4 v = *(const float4*)(Kbase + (size_t)(k0 + row) * DK + d0 + c4);
            Ks[c4 + 0][row] = v.x; Ks[c4 + 1][row] = v.y;
            Ks[c4 + 2][row] = v.z; Ks[c4 + 3][row] = v.w;
        }
        __syncthreads();
        #pragma unroll
        for (int kk = 0; kk < 32; kk++) {
            float a[8], bb[8];
            *(float4*)(a)      = *(float4*)&Qs[kk][ty * 8];
            *(float4*)(a + 4)  = *(float4*)&Qs[kk][ty * 8 + 4];
            *(float4*)(bb)     = *(float4*)&Ks[kk][tx * 8];
            *(float4*)(bb + 4) = *(float4*)&Ks[kk][tx * 8 + 4];
            #pragma unroll
            for (int i = 0; i < 8; i++)
                #pragma unroll
                for (int j = 0; j < 8; j++) acc[i][j] = fmaf(a[i], bb[j], acc[i][j]);
        }
        __syncthreads();
    }

    float* arow = attn + (size_t)bh * SEQ * SEQ;
    const int* mrow = mask + (size_t)b * SEQ * SEQ;
    #pragma unroll
    for (int i = 0; i < 8; i++) {
        int qi = q0 + ty * 8 + i;
        size_t off = (size_t)qi * SEQ + k0 + tx * 8;
        int4 mv0 = *(const int4*)(mrow + off);
        int4 mv1 = *(const int4*)(mrow + off + 4);
        float4 o0, o1;
        o0.x = mv0.x ? acc[i][0] : NEGV;
        o0.y = mv0.y ? acc[i][1] : NEGV;
        o0.z = mv0.z ? acc[i][2] : NEGV;
        o0.w = mv0.w ? acc[i][3] : NEGV;
        o1.x = mv1.x ? acc[i][4] : NEGV;
        o1.y = mv1.y ? acc[i][5] : NEGV;
        o1.z = mv1.z ? acc[i][6] : NEGV;
        o1.w = mv1.w ? acc[i][7] : NEGV;
        *(float4*)(arow + off)     = o0;
        *(float4*)(arow + off + 4) = o1;
    }
}

// ============================================================================
// Kernel 3: row softmax in place over attn.  One block per row (2048 elems).
// ============================================================================
__global__ __launch_bounds__(256)
void softmax_kernel(float* __restrict__ attn)
{
    const size_t base = (size_t)blockIdx.x * SEQ;
    const int tid = threadIdx.x;
    const int wid = tid >> 5, lane = tid & 31;

    float4 v0 = *(float4*)(attn + base + (size_t)tid * 4);
    float4 v1 = *(float4*)(attn + base + (size_t)(tid + 256) * 4);

    float m = fmaxf(fmaxf(fmaxf(v0.x, v0.y), fmaxf(v0.z, v0.w)),
                    fmaxf(fmaxf(v1.x, v1.y), fmaxf(v1.z, v1.w)));
    m = warp_max(m);
    __shared__ float red[8];
    if (lane == 0) red[wid] = m;
    __syncthreads();
    float bm = (lane < 8) ? red[lane] : -3.4e38f;
    bm = warp_max(bm);

    float e[8];
    e[0] = __expf(v0.x - bm); e[1] = __expf(v0.y - bm);
    e[2] = __expf(v0.z - bm); e[3] = __expf(v0.w - bm);
    e[4] = __expf(v1.x - bm); e[5] = __expf(v1.y - bm);
    e[6] = __expf(v1.z - bm); e[7] = __expf(v1.w - bm);
    float s = e[0] + e[1] + e[2] + e[3] + e[4] + e[5] + e[6] + e[7];
    s = warp_sum(s);
    __syncthreads();                       // red reuse hazard
    if (lane == 0) red[wid] = s;
    __syncthreads();
    float bs = (lane < 8) ? red[lane] : 0.0f;
    bs = warp_sum(bs);
    float inv = 1.0f / bs;

    float4 o0 = make_float4(e[0] * inv, e[1] * inv, e[2] * inv, e[3] * inv);
    float4 o1 = make_float4(e[4] * inv, e[5] * inv, e[6] * inv, e[7] * inv);
    *(float4*)(attn + base + (size_t)tid * 4)         = o0;
    *(float4*)(attn + base + (size_t)(tid + 256) * 4) = o1;
}

// ============================================================================
// Kernel 4: PV.  O[b,h,q,dv] = attn[b,h,q,:] @ V[b,h,:,dv], written merged
// into g_o[b,s,h*64+dv].  Tiles BM=128, BN=64, BK=32.  8x4 per thread.
// ============================================================================
__global__ __launch_bounds__(256)
void pv_kernel(const float* __restrict__ attn)
{
    const int bh = blockIdx.z;
    const int b  = bh >> 4;
    const int h  = bh & 15;
    const int q0 = blockIdx.y * 128;

    __shared__ float Ps[32][132];
    __shared__ float Vs[32][64];

    const int tid = threadIdx.x;
    const int tx  = tid & 15;   // *4 cols
    const int ty  = tid >> 4;   // *8 rows

    float acc[8][4];
    #pragma unroll
    for (int i = 0; i < 8; i++)
        #pragma unroll
        for (int j = 0; j < 4; j++) acc[i][j] = 0.0f;

    const float* abase = attn + (size_t)bh * SEQ * SEQ;
    const float* vbase = g_v + (size_t)bh * SEQ * DK;

    for (int k0 = 0; k0 < SEQ; k0 += 32) {
        #pragma unroll
        for (int t = 0; t < 4; t++) {
            int i4  = tid + t * 256;
            int row = i4 >> 3;                // 8 float4 per row of 32
            int c4  = (i4 & 7) * 4;
            float4 v = *(const float4*)(abase + (size_t)(q0 + row) * SEQ + k0 + c4);
            Ps[c4 + 0][row] = v.x; Ps[c4 + 1][row] = v.y;
            Ps[c4 + 2][row] = v.z; Ps[c4 + 3][row] = v.w;
        }
        #pragma unroll
        for (int t = 0; t < 2; t++) {
            int i4 = tid + t * 256;
            int r  = i4 >> 4;                 // 16 float4 per row of 64
            int c4 = (i4 & 15) * 4;
            *(float4*)&Vs[r][c4] =
                *(const float4*)(vbase + (size_t)(k0 + r) * DK + c4);
        }
        __syncthreads();
        #pragma unroll
        for (int kk = 0; kk < 32; kk++) {
            float a[8], bb[4];
            *(float4*)(a)     = *(float4*)&Ps[kk][ty * 8];
            *(float4*)(a + 4) = *(float4*)&Ps[kk][ty * 8 + 4];
            *(float4*)(bb)    = *(float4*)&Vs[kk][tx * 4];
            #pragma unroll
            for (int i = 0; i < 8; i++)
                #pragma unroll
                for (int j = 0; j < 4; j++) acc[i][j] = fmaf(a[i], bb[j], acc[i][j]);
        }
        __syncthreads();
    }
    #pragma unroll
    for (int i = 0; i < 8; i++) {
        int s = q0 + ty * 8 + i;
        *(float4*)(g_o + ((size_t)(b * SEQ + s)) * DMODEL + h * DK + tx * 4) =
            make_float4(acc[i][0], acc[i][1], acc[i][2], acc[i][3]);
    }
}

// ============================================================================
// Kernel 5: output projection + residual.  out = g_o @ w_fc + qkv  -> d_out.
// Same tiling as proj.
// ============================================================================
__global__ __launch_bounds__(256)
void fc_kernel(const float* __restrict__ w_fc,
               const float* __restrict__ qkv,
               float* __restrict__ out)
{
    const int n0 = blockIdx.x * 64;
    const int m0 = blockIdx.y * 128;

    __shared__ float As[16][132];
    __shared__ float Bsm[16][64];

    const int tid = threadIdx.x;
    const int tx  = tid & 15;
    const int ty  = tid >> 4;

    float acc[8][4];
    #pragma unroll
    for (int i = 0; i < 8; i++)
        #pragma unroll
        for (int j = 0; j < 4; j++) acc[i][j] = 0.0f;

    for (int k0 = 0; k0 < DMODEL; k0 += 16) {
        #pragma unroll
        for (int t = 0; t < 2; t++) {
            int i4  = tid + t * 256;
            int row = i4 >> 2;
            int c4  = (i4 & 3) * 4;
            float4 v = *(const float4*)(g_o + (size_t)(m0 + row) * DMODEL + k0 + c4);
            As[c4 + 0][row] = v.x; As[c4 + 1][row] = v.y;
            As[c4 + 2][row] = v.z; As[c4 + 3][row] = v.w;
        }
        {
            int r  = tid >> 4;
            int c4 = (tid & 15) * 4;
            *(float4*)&Bsm[r][c4] =
                *(const float4*)(w_fc + (size_t)(k0 + r) * DMODEL + n0 + c4);
        }
        __syncthreads();
        #pragma unroll
        for (int kk = 0; kk < 16; kk++) {
            float a[8], bb[4];
            *(float4*)(a)     = *(float4*)&As[kk][ty * 8];
            *(float4*)(a + 4) = *(float4*)&As[kk][ty * 8 + 4];
            *(float4*)(bb)    = *(float4*)&Bsm[kk][tx * 4];
            #pragma unroll
            for (int i = 0; i < 8; i++)
                #pragma unroll
                for (int j = 0; j < 4; j++) acc[i][j] = fmaf(a[i], bb[j], acc[i][j]);
        }
        __syncthreads();
    }
    #pragma unroll
    for (int i = 0; i < 8; i++) {
        int row = m0 + ty * 8 + i;
        float4 r = *(const float4*)(qkv + (size_t)row * DMODEL + n0 + tx * 4);
        float4 o = make_float4(acc[i][0] + r.x, acc[i][1] + r.y,
                               acc[i][2] + r.z, acc[i][3] + r.w);
        *(float4*)(out + (size_t)row * DMODEL + n0 + tx * 4) = o;
    }
}

// ============================================================================
// Kernel 6: LayerNorm in place on out rows (1024 elems each).
// ============================================================================
__global__ __launch_bounds__(256)
void ln_kernel(float* __restrict__ out,
               const float* __restrict__ gamma,
               const float* __restrict__ beta)
{
    const size_t base = (size_t)blockIdx.x * DMODEL;
    const int tid = threadIdx.x;
    const int wid = tid >> 5, lane = tid & 31;

    float4 v = *(float4*)(out + base + (size_t)tid * 4);
    float s  = v.x + v.y + v.z + v.w;
    float sq = v.x * v.x + v.y * v.y + v.z * v.z + v.w * v.w;
    s  = warp_sum(s);
    sq = warp_sum(sq);
    __shared__ float rs[8], rq[8];
    if (lane == 0) { rs[wid] = s; rq[wid] = sq; }
    __syncthreads();
    float ts = (lane < 8) ? rs[lane] : 0.0f; ts = warp_sum(ts);
    float tq = (lane < 8) ? rq[lane] : 0.0f; tq = warp_sum(tq);

    float mean = ts * (1.0f / DMODEL);
    float var  = tq * (1.0f / DMODEL) - mean * mean;
    float inv  = rsqrtf(var + 1e-6f);

    float4 g = *(const float4*)(gamma + tid * 4);
    float4 bt = *(const float4*)(beta + tid * 4);
    float4 o;
    o.x = (v.x - mean) * inv * g.x + bt.x;
    o.y = (v.y - mean) * inv * g.y + bt.y;
    o.z = (v.z - mean) * inv * g.z + bt.z;
    o.w = (v.w - mean) * inv * g.w + bt.w;
    *(float4*)(out + base + (size_t)tid * 4) = o;
}

// ============================================================================
extern "C" void kernel_launch(void* const* d_in, const int* in_sizes, int n_in,
                              void* d_out, int out_size)
{
    (void)in_sizes; (void)n_in; (void)out_size;
    const float* qkv    = (const float*)d_in[0];
    const int*   mask   = (const int*)  d_in[1];
    const float* w_qs   = (const float*)d_in[2];
    const float* w_ks   = (const float*)d_in[3];
    const float* w_vs   = (const float*)d_in[4];
    const float* w_fc   = (const float*)d_in[5];
    const float* ln_g   = (const float*)d_in[6];
    const float* ln_b   = (const float*)d_in[7];

    float* out_main = (float*)d_out;                 // [B,S,DMODEL]
    float* attn     = (float*)d_out + OUT_ELEMS;     // [B,H,S,S]

    proj_kernel   <<<dim3(NHEAD, BS / 128, 3), 256>>>(qkv, w_qs, w_ks, w_vs);
    scores_kernel <<<dim3(SEQ / 128, SEQ / 128, BATCH * NHEAD), 256>>>(mask, attn);
    softmax_kernel<<<BATCH * NHEAD * SEQ, 256>>>(attn);
    pv_kernel     <<<dim3(1, SEQ / 128, BATCH * NHEAD), 256>>>(attn);
    fc_kernel     <<<dim3(DMODEL / 64, BS / 128), 256>>>(w_fc, qkv, out_main);
    ln_kernel     <<<BS, 256>>>(out_main, ln_g, ln_b);
}

// round 5
// speedup vs baseline: 1.5412x; 1.5412x over previous
#include <cuda_runtime.h>
#include <cuda_bf16.h>
#include <cstdint>

#define NHEAD 16
#define DK 64
#define SEQ 2048
#define BATCH 2
#define DMODEL 1024
#define BS (BATCH*SEQ)
#define NEGV -1000000000.0f

static const size_t OUT_ELEMS = (size_t)BATCH * SEQ * DMODEL;   // 4,194,304

// -------- scratch (static device globals; no runtime allocation) --------
__device__ __nv_bfloat16 g_xhi[(size_t)BS * DMODEL];   // qkv split hi
__device__ __nv_bfloat16 g_xlo[(size_t)BS * DMODEL];   // qkv split lo
__device__ __nv_bfloat16 g_wqt_hi[(size_t)DMODEL * DMODEL];  // W^T planes [n][k]
__device__ __nv_bfloat16 g_wqt_lo[(size_t)DMODEL * DMODEL];
__device__ __nv_bfloat16 g_wkt_hi[(size_t)DMODEL * DMODEL];
__device__ __nv_bfloat16 g_wkt_lo[(size_t)DMODEL * DMODEL];
__device__ __nv_bfloat16 g_wft_hi[(size_t)DMODEL * DMODEL];
__device__ __nv_bfloat16 g_wft_lo[(size_t)DMODEL * DMODEL];
__device__ __nv_bfloat16 g_wvt  [(size_t)DMODEL * DMODEL];
__device__ __nv_bfloat16 g_qhi[(size_t)BATCH * NHEAD * SEQ * DK];
__device__ __nv_bfloat16 g_qlo[(size_t)BATCH * NHEAD * SEQ * DK];
__device__ __nv_bfloat16 g_khi[(size_t)BATCH * NHEAD * SEQ * DK];
__device__ __nv_bfloat16 g_klo[(size_t)BATCH * NHEAD * SEQ * DK];
__device__ __nv_bfloat16 g_vp [(size_t)BATCH * NHEAD * SEQ * DK];   // V [bh][s][64]
__device__ __nv_bfloat16 g_pb [(size_t)BATCH * NHEAD * SEQ * SEQ];  // bf16 softmax P
__device__ __nv_bfloat16 g_ohi[(size_t)BS * DMODEL];   // attention out hi
__device__ __nv_bfloat16 g_olo[(size_t)BS * DMODEL];   // attention out lo

// ======================= warp-MMA helpers =======================
__device__ __forceinline__ uint32_t smem_u32(const void* p) {
    uint32_t a;
    asm("{ .reg .u64 t; cvta.to.shared.u64 t, %1; cvt.u32.u64 %0, t; }" : "=r"(a) : "l"(p));
    return a;
}
__device__ __forceinline__ void ldsm4(uint32_t* r, uint32_t addr) {
    asm volatile("ldmatrix.sync.aligned.m8n8.x4.shared.b16 {%0,%1,%2,%3}, [%4];"
                 : "=r"(r[0]), "=r"(r[1]), "=r"(r[2]), "=r"(r[3]) : "r"(addr));
}
__device__ __forceinline__ void ldsm2(uint32_t* r, uint32_t addr) {
    asm volatile("ldmatrix.sync.aligned.m8n8.x2.shared.b16 {%0,%1}, [%2];"
                 : "=r"(r[0]), "=r"(r[1]) : "r"(addr));
}
__device__ __forceinline__ void ldsm2t(uint32_t* r, uint32_t addr) {
    asm volatile("ldmatrix.sync.aligned.m8n8.x2.trans.shared.b16 {%0,%1}, [%2];"
                 : "=r"(r[0]), "=r"(r[1]) : "r"(addr));
}
__device__ __forceinline__ void mma_bf(float* c, const uint32_t* a, const uint32_t* b) {
    asm volatile(
        "mma.sync.aligned.m16n8k16.row.col.f32.bf16.bf16.f32 "
        "{%0,%1,%2,%3}, {%4,%5,%6,%7}, {%8,%9}, {%0,%1,%2,%3};"
        : "+f"(c[0]), "+f"(c[1]), "+f"(c[2]), "+f"(c[3])
        : "r"(a[0]), "r"(a[1]), "r"(a[2]), "r"(a[3]), "r"(b[0]), "r"(b[1]));
}
__device__ __forceinline__ uint32_t pack_bf2f(float a, float b) {
    __nv_bfloat162 h = __floats2bfloat162_rn(a, b);
    return *reinterpret_cast<uint32_t*>(&h);
}
__device__ __forceinline__ void split2(float v0, float v1, uint32_t& hi, uint32_t& lo) {
    __nv_bfloat16 h0 = __float2bfloat16(v0), h1 = __float2bfloat16(v1);
    __nv_bfloat16 l0 = __float2bfloat16(v0 - __bfloat162float(h0));
    __nv_bfloat16 l1 = __float2bfloat16(v1 - __bfloat162float(h1));
    __nv_bfloat162 hh; hh.x = h0; hh.y = h1;
    __nv_bfloat162 ll; ll.x = l0; ll.y = l1;
    hi = *reinterpret_cast<uint32_t*>(&hh);
    lo = *reinterpret_cast<uint32_t*>(&ll);
}
__device__ __forceinline__ float warp_max(float v) {
    #pragma unroll
    for (int o = 16; o > 0; o >>= 1) v = fmaxf(v, __shfl_xor_sync(0xffffffffu, v, o));
    return v;
}
__device__ __forceinline__ float warp_sum(float v) {
    #pragma unroll
    for (int o = 16; o > 0; o >>= 1) v += __shfl_xor_sync(0xffffffffu, v, o);
    return v;
}

// ============================================================================
// prep 1: split qkv into bf16 hi/lo planes
// ============================================================================
__global__ __launch_bounds__(256)
void split_x(const float* __restrict__ x)
{
    size_t i = ((size_t)blockIdx.x * 256 + threadIdx.x) * 4;
    float4 v = *(const float4*)(x + i);
    uint32_t h0, l0, h1, l1;
    split2(v.x, v.y, h0, l0);
    split2(v.z, v.w, h1, l1);
    *(uint2*)(g_xhi + i) = make_uint2(h0, h1);
    *(uint2*)(g_xlo + i) = make_uint2(l0, l1);
}

// ============================================================================
// prep 2: transpose + split weights -> [n][k] bf16 planes
// z: 0=wq, 1=wk, 2=wv(hi only), 3=wfc
// ============================================================================
__global__ __launch_bounds__(256)
void wtrans(const float* __restrict__ wq, const float* __restrict__ wk,
            const float* __restrict__ wv, const float* __restrict__ wf)
{
    const int z = blockIdx.z;
    const float* W = (z == 0) ? wq : (z == 1) ? wk : (z == 2) ? wv : wf;
    __nv_bfloat16* Ohi = (z == 0) ? g_wqt_hi : (z == 1) ? g_wkt_hi : (z == 2) ? g_wvt : g_wft_hi;
    __nv_bfloat16* Olo = (z == 0) ? g_wqt_lo : (z == 1) ? g_wkt_lo : (z == 3) ? g_wft_lo : nullptr;

    __shared__ float t[32][33];
    const int n0 = blockIdx.x * 32, k0 = blockIdx.y * 32;
    const int tx = threadIdx.x & 31, ty = threadIdx.x >> 5;
    #pragma unroll
    for (int j = 0; j < 4; j++)
        t[ty + 8 * j][tx] = W[(size_t)(k0 + ty + 8 * j) * DMODEL + n0 + tx];
    __syncthreads();
    #pragma unroll
    for (int j = 0; j < 4; j++) {
        float v = t[tx][ty + 8 * j];
        __nv_bfloat16 h = __float2bfloat16(v);
        size_t off = (size_t)(n0 + ty + 8 * j) * DMODEL + k0 + tx;
        Ohi[off] = h;
        if (Olo) Olo[off] = __float2bfloat16(v - __bfloat162float(h));
    }
}

// ============================================================================
// GEMM Q/K projection (bf16x3): C[4096, head n0..n0+64] -> hi/lo planes
// CTA 128x64, 8 warps (4m x 2n), warp 32x32, k-chunk 32.
// ============================================================================
__global__ __launch_bounds__(256)
void gemm_qk()
{
    const int z = blockIdx.z;                  // 0=Q, 1=K
    const __nv_bfloat16* Whi = z ? g_wkt_hi : g_wqt_hi;
    const __nv_bfloat16* Wlo = z ? g_wkt_lo : g_wqt_lo;
    const int h  = blockIdx.x;
    const int n0 = h * 64;
    const int m0 = blockIdx.y * 128;

    __shared__ __align__(16) __nv_bfloat16 Ah[128 * 40], Al[128 * 40];
    __shared__ __align__(16) __nv_bfloat16 Bh[64 * 40],  Bl[64 * 40];

    const int tid = threadIdx.x;
    const int w = tid >> 5, lane = tid & 31;
    const int wm = w >> 1, wn = w & 1;

    const uint32_t uAh = smem_u32(Ah), uAl = smem_u32(Al);
    const uint32_t uBh = smem_u32(Bh), uBl = smem_u32(Bl);

    float c[2][4][4];
    #pragma unroll
    for (int mi = 0; mi < 2; mi++)
        #pragma unroll
        for (int ni = 0; ni < 4; ni++)
            #pragma unroll
            for (int r = 0; r < 4; r++) c[mi][ni][r] = 0.0f;

    for (int kc = 0; kc < 32; kc++) {
        const int k0 = kc * 32;
        #pragma unroll
        for (int t = 0; t < 2; t++) {
            int idx = tid + t * 256;
            int r = idx >> 2, cc = (idx & 3) * 8;
            *(uint4*)(Ah + r * 40 + cc) = *(const uint4*)(g_xhi + (size_t)(m0 + r) * DMODEL + k0 + cc);
            *(uint4*)(Al + r * 40 + cc) = *(const uint4*)(g_xlo + (size_t)(m0 + r) * DMODEL + k0 + cc);
        }
        {
            int r = tid >> 2, cc = (tid & 3) * 8;
            *(uint4*)(Bh + r * 40 + cc) = *(const uint4*)(Whi + (size_t)(n0 + r) * DMODEL + k0 + cc);
            *(uint4*)(Bl + r * 40 + cc) = *(const uint4*)(Wlo + (size_t)(n0 + r) * DMODEL + k0 + cc);
        }
        __syncthreads();
        #pragma unroll
        for (int ks = 0; ks < 2; ks++) {
            uint32_t ah[2][4], al[2][4], bh[4][2], bl[4][2];
            #pragma unroll
            for (int mi = 0; mi < 2; mi++) {
                uint32_t off = ((wm * 32 + mi * 16 + (lane & 15)) * 40 + (lane >> 4) * 8 + ks * 16) * 2;
                ldsm4(ah[mi], uAh + off);
                ldsm4(al[mi], uAl + off);
            }
            #pragma unroll
            for (int ni = 0; ni < 4; ni++) {
                uint32_t off = ((wn * 32 + ni * 8 + (lane & 7)) * 40 + ((lane >> 3) & 1) * 8 + ks * 16) * 2;
                ldsm2(bh[ni], uBh + off);
                ldsm2(bl[ni], uBl + off);
            }
            #pragma unroll
            for (int mi = 0; mi < 2; mi++)
                #pragma unroll
                for (int ni = 0; ni < 4; ni++) {
                    mma_bf(c[mi][ni], ah[mi], bh[ni]);
                    mma_bf(c[mi][ni], ah[mi], bl[ni]);
                    mma_bf(c[mi][ni], al[mi], bh[ni]);
                }
        }
        __syncthreads();
    }

    const float scale = z ? 1.0f : 0.125f;
    __nv_bfloat16* hiDst = z ? g_khi : g_qhi;
    __nv_bfloat16* loDst = z ? g_klo : g_qlo;
    #pragma unroll
    for (int mi = 0; mi < 2; mi++)
        #pragma unroll
        for (int ni = 0; ni < 4; ni++) {
            int col = wn * 32 + ni * 8 + (lane & 3) * 2;
            #pragma unroll
            for (int half = 0; half < 2; half++) {
                int row = m0 + wm * 32 + mi * 16 + (lane >> 2) + half * 8;
                int b = row >> 11, s = row & 2047;
                size_t off = ((size_t)((b * NHEAD + h) * SEQ + s)) * DK + col;
                uint32_t hi, lo;
                split2(c[mi][ni][half * 2] * scale, c[mi][ni][half * 2 + 1] * scale, hi, lo);
                *(uint32_t*)(hiDst + off) = hi;
                *(uint32_t*)(loDst + off) = lo;
            }
        }
}

// ============================================================================
// GEMM V projection (plain bf16): same shape, single plane.
// ============================================================================
__global__ __launch_bounds__(256)
void gemm_v()
{
    const int h  = blockIdx.x;
    const int n0 = h * 64;
    const int m0 = blockIdx.y * 128;

    __shared__ __align__(16) __nv_bfloat16 Ah[128 * 40];
    __shared__ __align__(16) __nv_bfloat16 Bh[64 * 40];

    const int tid = threadIdx.x;
    const int w = tid >> 5, lane = tid & 31;
    const int wm = w >> 1, wn = w & 1;
    const uint32_t uAh = smem_u32(Ah), uBh = smem_u32(Bh);

    float c[2][4][4];
    #pragma unroll
    for (int mi = 0; mi < 2; mi++)
        #pragma unroll
        for (int ni = 0; ni < 4; ni++)
            #pragma unroll
            for (int r = 0; r < 4; r++) c[mi][ni][r] = 0.0f;

    for (int kc = 0; kc < 32; kc++) {
        const int k0 = kc * 32;
        #pragma unroll
        for (int t = 0; t < 2; t++) {
            int idx = tid + t * 256;
            int r = idx >> 2, cc = (idx & 3) * 8;
            *(uint4*)(Ah + r * 40 + cc) = *(const uint4*)(g_xhi + (size_t)(m0 + r) * DMODEL + k0 + cc);
        }
        {
            int r = tid >> 2, cc = (tid & 3) * 8;
            *(uint4*)(Bh + r * 40 + cc) = *(const uint4*)(g_wvt + (size_t)(n0 + r) * DMODEL + k0 + cc);
        }
        __syncthreads();
        #pragma unroll
        for (int ks = 0; ks < 2; ks++) {
            uint32_t ah[2][4], bh[4][2];
            #pragma unroll
            for (int mi = 0; mi < 2; mi++)
                ldsm4(ah[mi], uAh + ((wm * 32 + mi * 16 + (lane & 15)) * 40 + (lane >> 4) * 8 + ks * 16) * 2);
            #pragma unroll
            for (int ni = 0; ni < 4; ni++)
                ldsm2(bh[ni], uBh + ((wn * 32 + ni * 8 + (lane & 7)) * 40 + ((lane >> 3) & 1) * 8 + ks * 16) * 2);
            #pragma unroll
            for (int mi = 0; mi < 2; mi++)
                #pragma unroll
                for (int ni = 0; ni < 4; ni++)
                    mma_bf(c[mi][ni], ah[mi], bh[ni]);
        }
        __syncthreads();
    }

    #pragma unroll
    for (int mi = 0; mi < 2; mi++)
        #pragma unroll
        for (int ni = 0; ni < 4; ni++) {
            int col = wn * 32 + ni * 8 + (lane & 3) * 2;
            #pragma unroll
            for (int half = 0; half < 2; half++) {
                int row = m0 + wm * 32 + mi * 16 + (lane >> 2) + half * 8;
                int b = row >> 11, s = row & 2047;
                size_t off = ((size_t)((b * NHEAD + h) * SEQ + s)) * DK + col;
                *(uint32_t*)(g_vp + off) =
                    pack_bf2f(c[mi][ni][half * 2], c[mi][ni][half * 2 + 1]);
            }
        }
}

// ============================================================================
// Scores (bf16x3): attn_raw[bh, q, k] with mask.  CTA 128x128, 8 warps (2m x 4n),
// warp 64x32.  K = 64 (full), tiles Qhi/Qlo/Khi/Klo 128x64 stride 72.
// ============================================================================
static constexpr int SC_T = 128 * 72;                    // elems per tile
static constexpr int SC_BYTES = 4 * SC_T * 2;            // 73728

__global__ __launch_bounds__(256)
void scores_mm(const int* __restrict__ mask, float* __restrict__ attn)
{
    extern __shared__ __align__(16) __nv_bfloat16 smem[];
    __nv_bfloat16* sQh = smem;
    __nv_bfloat16* sQl = smem + SC_T;
    __nv_bfloat16* sKh = smem + 2 * SC_T;
    __nv_bfloat16* sKl = smem + 3 * SC_T;

    const int tid = threadIdx.x;
    const int w = tid >> 5, lane = tid & 31;
    const int wm = w >> 2, wn = w & 3;       // 2 x 4
    const int k0 = blockIdx.x * 128;
    const int q0 = blockIdx.y * 128;
    const int bh = blockIdx.z;
    const int b  = bh >> 4;

    const size_t plane = (size_t)bh * SEQ * DK;
    const __nv_bfloat16* srcs[4] = {
        g_qhi + plane + (size_t)q0 * DK, g_qlo + plane + (size_t)q0 * DK,
        g_khi + plane + (size_t)k0 * DK, g_klo + plane + (size_t)k0 * DK };
    __nv_bfloat16* dsts[4] = { sQh, sQl, sKh, sKl };
    #pragma unroll
    for (int t = 0; t < 4; t++)
        for (int idx = tid; idx < 1024; idx += 256) {
            int r = idx >> 3, cc = (idx & 7) * 8;
            *(uint4*)(dsts[t] + r * 72 + cc) = *(const uint4*)(srcs[t] + (size_t)r * DK + cc);
        }
    __syncthreads();

    const uint32_t uQh = smem_u32(sQh), uQl = smem_u32(sQl);
    const uint32_t uKh = smem_u32(sKh), uKl = smem_u32(sKl);

    float c[4][4][4];
    #pragma unroll
    for (int mi = 0; mi < 4; mi++)
        #pragma unroll
        for (int ni = 0; ni < 4; ni++)
            #pragma unroll
            for (int r = 0; r < 4; r++) c[mi][ni][r] = 0.0f;

    #pragma unroll
    for (int pass = 0; pass < 3; pass++) {
        const uint32_t uA = (pass == 2) ? uQl : uQh;
        const uint32_t uB = (pass == 1) ? uKl : uKh;
        #pragma unroll
        for (int ks = 0; ks < 4; ks++) {
            uint32_t a[4][4], bf[4][2];
            #pragma unroll
            for (int mi = 0; mi < 4; mi++)
                ldsm4(a[mi], uA + ((wm * 64 + mi * 16 + (lane & 15)) * 72 + (lane >> 4) * 8 + ks * 16) * 2);
            #pragma unroll
            for (int ni = 0; ni < 4; ni++)
                ldsm2(bf[ni], uB + ((wn * 32 + ni * 8 + (lane & 7)) * 72 + ((lane >> 3) & 1) * 8 + ks * 16) * 2);
            #pragma unroll
            for (int mi = 0; mi < 4; mi++)
                #pragma unroll
                for (int ni = 0; ni < 4; ni++)
                    mma_bf(c[mi][ni], a[mi], bf[ni]);
        }
    }

    float* aplane = attn + (size_t)bh * SEQ * SEQ;
    const int* mplane = mask + (size_t)b * SEQ * SEQ;
    #pragma unroll
    for (int mi = 0; mi < 4; mi++)
        #pragma unroll
        for (int ni = 0; ni < 4; ni++) {
            int kcol = k0 + wn * 32 + ni * 8 + (lane & 3) * 2;
            #pragma unroll
            for (int half = 0; half < 2; half++) {
                int qrow = q0 + wm * 64 + mi * 16 + (lane >> 2) + half * 8;
                size_t off = (size_t)qrow * SEQ + kcol;
                int2 mv = *(const int2*)(mplane + off);
                float2 o;
                o.x = mv.x ? c[mi][ni][half * 2]     : NEGV;
                o.y = mv.y ? c[mi][ni][half * 2 + 1] : NEGV;
                *(float2*)(aplane + off) = o;
            }
        }
}

// ============================================================================
// Softmax in place; also emits bf16 P plane.
// ============================================================================
__global__ __launch_bounds__(256)
void softmax_kernel(float* __restrict__ attn)
{
    const size_t base = (size_t)blockIdx.x * SEQ;
    const int tid = threadIdx.x;
    const int wid = tid >> 5, lane = tid & 31;

    float4 v0 = *(float4*)(attn + base + (size_t)tid * 4);
    float4 v1 = *(float4*)(attn + base + (size_t)(tid + 256) * 4);

    float m = fmaxf(fmaxf(fmaxf(v0.x, v0.y), fmaxf(v0.z, v0.w)),
                    fmaxf(fmaxf(v1.x, v1.y), fmaxf(v1.z, v1.w)));
    m = warp_max(m);
    __shared__ float red[8];
    if (lane == 0) red[wid] = m;
    __syncthreads();
    float bm = (lane < 8) ? red[lane] : -3.4e38f;
    bm = warp_max(bm);

    float e[8];
    e[0] = __expf(v0.x - bm); e[1] = __expf(v0.y - bm);
    e[2] = __expf(v0.z - bm); e[3] = __expf(v0.w - bm);
    e[4] = __expf(v1.x - bm); e[5] = __expf(v1.y - bm);
    e[6] = __expf(v1.z - bm); e[7] = __expf(v1.w - bm);
    float s = e[0] + e[1] + e[2] + e[3] + e[4] + e[5] + e[6] + e[7];
    s = warp_sum(s);
    __syncthreads();
    if (lane == 0) red[wid] = s;
    __syncthreads();
    float bs = (lane < 8) ? red[lane] : 0.0f;
    bs = warp_sum(bs);
    float inv = 1.0f / bs;

    float p[8];
    #pragma unroll
    for (int i = 0; i < 8; i++) p[i] = e[i] * inv;

    *(float4*)(attn + base + (size_t)tid * 4)         = make_float4(p[0], p[1], p[2], p[3]);
    *(float4*)(attn + base + (size_t)(tid + 256) * 4) = make_float4(p[4], p[5], p[6], p[7]);

    *(uint2*)(g_pb + base + (size_t)tid * 4) =
        make_uint2(pack_bf2f(p[0], p[1]), pack_bf2f(p[2], p[3]));
    *(uint2*)(g_pb + base + (size_t)(tid + 256) * 4) =
        make_uint2(pack_bf2f(p[4], p[5]), pack_bf2f(p[6], p[7]));
}

// ============================================================================
// PV (plain bf16): O[q, d] = P[q, s] @ V[s, d].  CTA 128q x 64d, 8 warps (4m x 2n),
// warp 32x32, k-chunk 64.  V tile loaded natural [s][d], B frags via ldmatrix.trans.
// Emits O as hi/lo bf16 planes at [row][h*64+d].
// ============================================================================
__global__ __launch_bounds__(256)
void pv_mm()
{
    __shared__ __align__(16) __nv_bfloat16 Ps[128 * 72];
    __shared__ __align__(16) __nv_bfloat16 Vs[64 * 72];

    const int tid = threadIdx.x;
    const int w = tid >> 5, lane = tid & 31;
    const int wm = w >> 1, wn = w & 1;       // 4 x 2
    const int q0 = blockIdx.x * 128;
    const int bh = blockIdx.y;
    const int b  = bh >> 4, h = bh & 15;

    const uint32_t uP = smem_u32(Ps), uV = smem_u32(Vs);
    const __nv_bfloat16* pb = g_pb + (size_t)bh * SEQ * SEQ + (size_t)q0 * SEQ;
    const __nv_bfloat16* vp = g_vp + (size_t)bh * SEQ * DK;

    float c[2][4][4];
    #pragma unroll
    for (int mi = 0; mi < 2; mi++)
        #pragma unroll
        for (int ni = 0; ni < 4; ni++)
            #pragma unroll
            for (int r = 0; r < 4; r++) c[mi][ni][r] = 0.0f;

    for (int kc = 0; kc < 32; kc++) {
        const int s0 = kc * 64;
        #pragma unroll
        for (int t = 0; t < 4; t++) {
            int idx = tid + t * 256;
            int r = idx >> 3, cc = (idx & 7) * 8;
            *(uint4*)(Ps + r * 72 + cc) = *(const uint4*)(pb + (size_t)r * SEQ + s0 + cc);
        }
        #pragma unroll
        for (int t = 0; t < 2; t++) {
            int idx = tid + t * 256;
            int r = idx >> 3, cc = (idx & 7) * 8;
            *(uint4*)(Vs + r * 72 + cc) = *(const uint4*)(vp + (size_t)(s0 + r) * DK + cc);
        }
        __syncthreads();
        #pragma unroll
        for (int ks = 0; ks < 4; ks++) {
            uint32_t a[2][4], bf[4][2];
            #pragma unroll
            for (int mi = 0; mi < 2; mi++)
                ldsm4(a[mi], uP + ((wm * 32 + mi * 16 + (lane & 15)) * 72 + (lane >> 4) * 8 + ks * 16) * 2);
            #pragma unroll
            for (int ni = 0; ni < 4; ni++)
                ldsm2t(bf[ni], uV + ((ks * 16 + (lane & 15)) * 72 + wn * 32 + ni * 8) * 2);
            #pragma unroll
            for (int mi = 0; mi < 2; mi++)
                #pragma unroll
                for (int ni = 0; ni < 4; ni++)
                    mma_bf(c[mi][ni], a[mi], bf[ni]);
        }
        __syncthreads();
    }

    #pragma unroll
    for (int mi = 0; mi < 2; mi++)
        #pragma unroll
        for (int ni = 0; ni < 4; ni++) {
            int d = wn * 32 + ni * 8 + (lane & 3) * 2;
            #pragma unroll
            for (int half = 0; half < 2; half++) {
                int s = q0 + wm * 32 + mi * 16 + (lane >> 2) + half * 8;
                size_t off = (size_t)(b * SEQ + s) * DMODEL + h * DK + d;
                uint32_t hi, lo;
                split2(c[mi][ni][half * 2], c[mi][ni][half * 2 + 1], hi, lo);
                *(uint32_t*)(g_ohi + off) = hi;
                *(uint32_t*)(g_olo + off) = lo;
            }
        }
}

// ============================================================================
// FC (bf16x3) + residual: out = O @ wfc + qkv.  Same shape as gemm_qk.
// ============================================================================
__global__ __launch_bounds__(256)
void gemm_fc(const float* __restrict__ qkv, float* __restrict__ out)
{
    const int n0 = blockIdx.x * 64;
    const int m0 = blockIdx.y * 128;

    __shared__ __align__(16) __nv_bfloat16 Ah[128 * 40], Al[128 * 40];
    __shared__ __align__(16) __nv_bfloat16 Bh[64 * 40],  Bl[64 * 40];

    const int tid = threadIdx.x;
    const int w = tid >> 5, lane = tid & 31;
    const int wm = w >> 1, wn = w & 1;
    const uint32_t uAh = smem_u32(Ah), uAl = smem_u32(Al);
    const uint32_t uBh = smem_u32(Bh), uBl = smem_u32(Bl);

    float c[2][4][4];
    #pragma unroll
    for (int mi = 0; mi < 2; mi++)
        #pragma unroll
        for (int ni = 0; ni < 4; ni++)
            #pragma unroll
            for (int r = 0; r < 4; r++) c[mi][ni][r] = 0.0f;

    for (int kc = 0; kc < 32; kc++) {
        const int k0 = kc * 32;
        #pragma unroll
        for (int t = 0; t < 2; t++) {
            int idx = tid + t * 256;
            int r = idx >> 2, cc = (idx & 3) * 8;
            *(uint4*)(Ah + r * 40 + cc) = *(const uint4*)(g_ohi + (size_t)(m0 + r) * DMODEL + k0 + cc);
            *(uint4*)(Al + r * 40 + cc) = *(const uint4*)(g_olo + (size_t)(m0 + r) * DMODEL + k0 + cc);
        }
        {
            int r = tid >> 2, cc = (tid & 3) * 8;
            *(uint4*)(Bh + r * 40 + cc) = *(const uint4*)(g_wft_hi + (size_t)(n0 + r) * DMODEL + k0 + cc);
            *(uint4*)(Bl + r * 40 + cc) = *(const uint4*)(g_wft_lo + (size_t)(n0 + r) * DMODEL + k0 + cc);
        }
        __syncthreads();
        #pragma unroll
        for (int ks = 0; ks < 2; ks++) {
            uint32_t ah[2][4], al[2][4], bh[4][2], bl[4][2];
            #pragma unroll
            for (int mi = 0; mi < 2; mi++) {
                uint32_t off = ((wm * 32 + mi * 16 + (lane & 15)) * 40 + (lane >> 4) * 8 + ks * 16) * 2;
                ldsm4(ah[mi], uAh + off);
                ldsm4(al[mi], uAl + off);
            }
            #pragma unroll
            for (int ni = 0; ni < 4; ni++) {
                uint32_t off = ((wn * 32 + ni * 8 + (lane & 7)) * 40 + ((lane >> 3) & 1) * 8 + ks * 16) * 2;
                ldsm2(bh[ni], uBh + off);
                ldsm2(bl[ni], uBl + off);
            }
            #pragma unroll
            for (int mi = 0; mi < 2; mi++)
                #pragma unroll
                for (int ni = 0; ni < 4; ni++) {
                    mma_bf(c[mi][ni], ah[mi], bh[ni]);
                    mma_bf(c[mi][ni], ah[mi], bl[ni]);
                    mma_bf(c[mi][ni], al[mi], bh[ni]);
                }
        }
        __syncthreads();
    }

    #pragma unroll
    for (int mi = 0; mi < 2; mi++)
        #pragma unroll
        for (int ni = 0; ni < 4; ni++) {
            int col = n0 + wn * 32 + ni * 8 + (lane & 3) * 2;
            #pragma unroll
            for (int half = 0; half < 2; half++) {
                int row = m0 + wm * 32 + mi * 16 + (lane >> 2) + half * 8;
                size_t off = (size_t)row * DMODEL + col;
                float2 r = *(const float2*)(qkv + off);
                *(float2*)(out + off) =
                    make_float2(c[mi][ni][half * 2] + r.x, c[mi][ni][half * 2 + 1] + r.y);
            }
        }
}

// ============================================================================
// LayerNorm in place.
// ============================================================================
__global__ __launch_bounds__(256)
void ln_kernel(float* __restrict__ out,
               const float* __restrict__ gamma,
               const float* __restrict__ beta)
{
    const size_t base = (size_t)blockIdx.x * DMODEL;
    const int tid = threadIdx.x;
    const int wid = tid >> 5, lane = tid & 31;

    float4 v = *(float4*)(out + base + (size_t)tid * 4);
    float s  = v.x + v.y + v.z + v.w;
    float sq = v.x * v.x + v.y * v.y + v.z * v.z + v.w * v.w;
    s  = warp_sum(s);
    sq = warp_sum(sq);
    __shared__ float rs[8], rq[8];
    if (lane == 0) { rs[wid] = s; rq[wid] = sq; }
    __syncthreads();
    float ts = (lane < 8) ? rs[lane] : 0.0f; ts = warp_sum(ts);
    float tq = (lane < 8) ? rq[lane] : 0.0f; tq = warp_sum(tq);

    float mean = ts * (1.0f / DMODEL);
    float var  = tq * (1.0f / DMODEL) - mean * mean;
    float inv  = rsqrtf(var + 1e-6f);

    float4 g  = *(const float4*)(gamma + tid * 4);
    float4 bt = *(const float4*)(beta + tid * 4);
    float4 o;
    o.x = (v.x - mean) * inv * g.x + bt.x;
    o.y = (v.y - mean) * inv * g.y + bt.y;
    o.z = (v.z - mean) * inv * g.z + bt.z;
    o.w = (v.w - mean) * inv * g.w + bt.w;
    *(float4*)(out + base + (size_t)tid * 4) = o;
}

// ============================================================================
extern "C" void kernel_launch(void* const* d_in, const int* in_sizes, int n_in,
                              void* d_out, int out_size)
{
    (void)in_sizes; (void)n_in; (void)out_size;
    const float* qkv  = (const float*)d_in[0];
    const int*   mask = (const int*)  d_in[1];
    const float* w_qs = (const float*)d_in[2];
    const float* w_ks = (const float*)d_in[3];
    const float* w_vs = (const float*)d_in[4];
    const float* w_fc = (const float*)d_in[5];
    const float* ln_g = (const float*)d_in[6];
    const float* ln_b = (const float*)d_in[7];

    float* out_main = (float*)d_out;
    float* attn     = (float*)d_out + OUT_ELEMS;

    static bool attr_set = false;
    if (!attr_set) {
        cudaFuncSetAttribute(scores_mm, cudaFuncAttributeMaxDynamicSharedMemorySize, SC_BYTES);
        attr_set = true;
    }

    split_x   <<<BS * DMODEL / 4 / 256, 256>>>(qkv);
    wtrans    <<<dim3(32, 32, 4), 256>>>(w_qs, w_ks, w_vs, w_fc);
    gemm_qk   <<<dim3(NHEAD, BS / 128, 2), 256>>>();
    gemm_v    <<<dim3(NHEAD, BS / 128), 256>>>();
    scores_mm <<<dim3(SEQ / 128, SEQ / 128, BATCH * NHEAD), 256, SC_BYTES>>>(mask, attn);
    softmax_kernel<<<BATCH * NHEAD * SEQ, 256>>>(attn);
    pv_mm     <<<dim3(SEQ / 128, BATCH * NHEAD), 256>>>();
    gemm_fc   <<<dim3(DMODEL / 64, BS / 128), 256>>>(qkv, out_main);
    ln_kernel <<<BS, 256>>>(out_main, ln_g, ln_b);
}